// round 11
// baseline (speedup 1.0000x reference)
#include <cuda_runtime.h>
#include <cstdint>

// BatchedHGNNLayer: out = diag(Dv^-1/2) H diag(De^-1) H^T diag(Dv^-1/2) x W^T + b
// B=8, N=4096, E=2048, C=128 fp32. mma.sync tf32 + cp.async + ldmatrix frags
// + in-smem tile rounding (no per-fragment cvt).

#define B_ 8
#define N_ 4096
#define E_ 2048
#define C_ 128
#define EPS 1e-6f

// ---------------- scratch ----------------------------------------------------
__device__ float g_DvInv[B_ * N_];
__device__ float g_XT[(size_t)B_ * C_ * N_];    // rna(x*Dv)^T   [b][c][n]
__device__ float g_M2T[(size_t)B_ * C_ * E_];   // rna((De^-1 H^T Xs) W^T)^T [b][c2][e]

// ---------------- helpers ----------------------------------------------------
__device__ __forceinline__ float tf32r(float x) {
    uint32_t u;
    asm("cvt.rna.tf32.f32 %0, %1;" : "=r"(u) : "f"(x));
    return __uint_as_float(u);
}
__device__ __forceinline__ uint32_t tf32u(float x) {
    uint32_t u;
    asm("cvt.rna.tf32.f32 %0, %1;" : "=r"(u) : "f"(x));
    return u;
}
__device__ __forceinline__ uint32_t smem_u32(const void* p) {
    uint32_t a;
    asm("{ .reg .u64 t; cvta.to.shared.u64 t, %1; cvt.u32.u64 %0, t; }" : "=r"(a) : "l"(p));
    return a;
}
__device__ __forceinline__ void mma_tf32(float* c, const uint32_t* a, const uint32_t* b) {
    asm volatile(
        "mma.sync.aligned.m16n8k8.row.col.f32.tf32.tf32.f32 "
        "{%0,%1,%2,%3}, {%4,%5,%6,%7}, {%8,%9}, {%0,%1,%2,%3};"
        : "+f"(c[0]), "+f"(c[1]), "+f"(c[2]), "+f"(c[3])
        : "r"(a[0]), "r"(a[1]), "r"(a[2]), "r"(a[3]), "r"(b[0]), "r"(b[1]));
}
#define CP16(dst, src) \
    asm volatile("cp.async.cg.shared.global [%0], [%1], 16;" :: "r"(dst), "l"(src))
#define CP_COMMIT() asm volatile("cp.async.commit_group;" ::: "memory")
#define CP_WAIT(n)  asm volatile("cp.async.wait_group %0;" :: "n"(n) : "memory")
#define FU(x) __float_as_uint(x)
// tf32 fragment load via b16 ldmatrix (tile = 8 rows x 4 tf32 = 8x16B)
#define LDSM4(r0, r1, r2, r3, addr)                                             \
    asm volatile("ldmatrix.sync.aligned.m8n8.x4.shared.b16 {%0,%1,%2,%3}, [%4];"\
                 : "=r"(r0), "=r"(r1), "=r"(r2), "=r"(r3) : "r"(addr))

// ---------------- small kernels ----------------------------------------------
__global__ void dv_kernel(const float* __restrict__ Hg) {
    int row = blockIdx.x * 8 + threadIdx.y;
    const float4* src = (const float4*)(Hg + (size_t)row * E_);
    float s = 0.f;
    for (int i = threadIdx.x; i < E_ / 4; i += 32) {
        float4 v = src[i];
        s += (v.x + v.y) + (v.z + v.w);
    }
    #pragma unroll
    for (int o = 16; o; o >>= 1) s += __shfl_xor_sync(0xffffffffu, s, o);
    if (threadIdx.x == 0) g_DvInv[row] = rsqrtf(s + EPS);
}

// XT[b][c][n] = rna(x[b][n][c] * DvInv[b][n])
__global__ void prep_xt(const float* __restrict__ xg) {
    __shared__ float t[32][33];
    int b = blockIdx.z, n0 = blockIdx.x * 32, c0 = blockIdx.y * 32;
    const float* xb = xg + ((size_t)b * N_ + n0) * C_ + c0;
    for (int r = threadIdx.y; r < 32; r += 8)
        t[r][threadIdx.x] = xb[(size_t)r * C_ + threadIdx.x] * g_DvInv[b * N_ + n0 + r];
    __syncthreads();
    float* XTb = g_XT + ((size_t)b * C_ + c0) * N_ + n0;
    for (int r = threadIdx.y; r < 32; r += 8)
        XTb[(size_t)r * N_ + threadIdx.x] = tf32r(t[threadIdx.x][r]);
}

// ---------------- GEMM1 (+De, +fused W M^T): BM=128 ------------------------
// A (KM): H[n][e-tile] -> smem [k=32][m=136]; B (MK): XT[c][n] -> smem [128][36]
#define TA1 (32 * 136 * 4)    // 17408
#define TB1 (128 * 36 * 4)    // 18432
#define DYN1 (4 * TA1 + 4 * TB1)  // 143360

__global__ __launch_bounds__(256, 1) void gemm1_kernel(const float* __restrict__ Hg,
                                                       const float* __restrict__ Wg) {
    extern __shared__ __align__(16) char ds[];
    __shared__ float deP[8][128];
    __shared__ float scl[128];

    const int tid = threadIdx.x, b = blockIdx.z, blk = blockIdx.x;
    const int lane = tid & 31, wid = tid >> 5;
    const int g = lane >> 2, tg = lane & 3;
    const int wm = wid & 1, wn = wid >> 1;
    const int lm = ((lane >> 3) & 1) * 8 + (lane & 7);   // ldmatrix row comp
    const int lk = (lane >> 4) * 4;                      // ldmatrix col comp

    const float* Ag = Hg + (size_t)b * N_ * E_;
    const float* Bg = g_XT + (size_t)b * C_ * N_;
    const int acol = blk * 128;

    const uint32_t sA = smem_u32(ds), sB = sA + 4 * TA1;

    float acc[4][4][4];
    #pragma unroll
    for (int i = 0; i < 4; i++)
        #pragma unroll
        for (int j = 0; j < 4; j++)
            #pragma unroll
            for (int r = 0; r < 4; r++) acc[i][j][r] = 0.f;

    float de4[4] = {0.f, 0.f, 0.f, 0.f};

    auto issue = [&](int kt) {
        int buf = kt & 3;
        #pragma unroll
        for (int i = 0; i < 4; i++) {
            int ch = tid + 256 * i;
            int k = ch >> 5, m4 = (ch & 31) * 4;         // A: 32k x 128m
            CP16(sA + buf * TA1 + (k * 136 + m4) * 4,
                 Ag + (size_t)(kt * 32 + k) * E_ + acol + m4);
            int m = ch >> 3, k4 = (ch & 7) * 4;          // B: 128c x 32k
            CP16(sB + buf * TB1 + (m * 36 + k4) * 4,
                 Bg + (size_t)m * N_ + kt * 32 + k4);
        }
        CP_COMMIT();
    };

    const int KT = N_ / 32;   // 128
    issue(0); issue(1); issue(2);

    for (int kt = 0; kt < KT; kt++) {
        if (kt + 3 < KT) issue(kt + 3);
        int rem = KT - 1 - kt;
        if (rem >= 3)      CP_WAIT(3);
        else if (rem == 2) CP_WAIT(2);
        else if (rem == 1) CP_WAIT(1);
        else               CP_WAIT(0);
        __syncthreads();

        float* As = (float*)(ds + (size_t)(kt & 3) * TA1);
        const uint32_t sBb = sB + (uint32_t)(kt & 3) * TB1;

        // ---- rounding + De pass on raw-H A tile (in place) ----
        {
            const int kbase = tid >> 5, m4 = (tid & 31) * 4;
            #pragma unroll
            for (int i = 0; i < 4; i++) {
                float4 v = *(float4*)(As + (kbase + 8 * i) * 136 + m4);
                de4[0] += v.x; de4[1] += v.y; de4[2] += v.z; de4[3] += v.w;
                v.x = tf32r(v.x); v.y = tf32r(v.y); v.z = tf32r(v.z); v.w = tf32r(v.w);
                *(float4*)(As + (kbase + 8 * i) * 136 + m4) = v;
            }
        }
        __syncthreads();

        #pragma unroll
        for (int ks = 0; ks < 32; ks += 8) {
            uint32_t af[4][4], bf[4][2];
            #pragma unroll
            for (int mt = 0; mt < 4; mt++) {
                int m = wm * 64 + mt * 16 + g;
                af[mt][0] = FU(As[(ks + tg) * 136 + m]);
                af[mt][1] = FU(As[(ks + tg) * 136 + m + 8]);
                af[mt][2] = FU(As[(ks + tg + 4) * 136 + m]);
                af[mt][3] = FU(As[(ks + tg + 4) * 136 + m + 8]);
            }
            #pragma unroll
            for (int p = 0; p < 2; p++) {
                uint32_t t0, t1, t2, t3;
                uint32_t addr = sBb + (uint32_t)(((wn * 32 + p * 16 + lm) * 36 + ks + lk) * 4);
                LDSM4(t0, t1, t2, t3, addr);
                bf[2 * p][0] = t0; bf[2 * p + 1][0] = t1;
                bf[2 * p][1] = t2; bf[2 * p + 1][1] = t3;
            }
            #pragma unroll
            for (int mt = 0; mt < 4; mt++)
                #pragma unroll
                for (int nt = 0; nt < 4; nt++)
                    mma_tf32(acc[mt][nt], af[mt], bf[nt]);
        }
        __syncthreads();
    }

    // ---- epilogue: W load + De combine + in-CTA sub-GEMM M2T = W M^T ----
    float* Msm = (float*)ds;                     // [128][132] = 67584 B (A-ring)
    float* Wsm = (float*)(ds + 4 * TA1);         // [128][132] = 67584 B (B-ring)
    {
        const uint32_t sW = smem_u32(Wsm);
        #pragma unroll
        for (int i = 0; i < 16; i++) {
            int ch = tid + 256 * i;              // 4096 chunks: 128 rows x 32
            int m = ch >> 5, q = ch & 31;
            CP16(sW + (m * 132 + q * 4) * 4, Wg + (size_t)m * C_ + q * 4);
        }
        CP_COMMIT();
    }
    *(float4*)&deP[tid >> 5][(tid & 31) * 4] = make_float4(de4[0], de4[1], de4[2], de4[3]);
    __syncthreads();
    if (tid < 128) {
        float t = EPS;
        #pragma unroll
        for (int j = 0; j < 8; j++) t += deP[j][tid];
        scl[tid] = 1.0f / t;
    }
    __syncthreads();

    #pragma unroll
    for (int mt = 0; mt < 4; mt++) {
        int r = wm * 64 + mt * 16 + g;
        float s0 = scl[r], s1 = scl[r + 8];
        #pragma unroll
        for (int nt = 0; nt < 4; nt++) {
            int col = wn * 32 + nt * 8 + tg * 2;
            float* c = acc[mt][nt];
            *(float2*)(Msm + r * 132 + col) =
                make_float2(tf32r(c[0] * s0), tf32r(c[1] * s0));
            *(float2*)(Msm + (r + 8) * 132 + col) =
                make_float2(tf32r(c[2] * s1), tf32r(c[3] * s1));
        }
    }
    CP_WAIT(0);
    __syncthreads();

    float acc2[4][4][4];
    #pragma unroll
    for (int i = 0; i < 4; i++)
        #pragma unroll
        for (int j = 0; j < 4; j++)
            #pragma unroll
            for (int r = 0; r < 4; r++) acc2[i][j][r] = 0.f;

    for (int ks = 0; ks < 128; ks += 8) {
        uint32_t af[4][4], bf[4][2];
        #pragma unroll
        for (int mt = 0; mt < 4; mt++) {
            int m = wm * 64 + mt * 16 + g;
            af[mt][0] = tf32u(Wsm[m * 132 + ks + tg]);
            af[mt][1] = tf32u(Wsm[(m + 8) * 132 + ks + tg]);
            af[mt][2] = tf32u(Wsm[m * 132 + ks + tg + 4]);
            af[mt][3] = tf32u(Wsm[(m + 8) * 132 + ks + tg + 4]);
        }
        #pragma unroll
        for (int nt = 0; nt < 4; nt++) {
            int n = wn * 32 + nt * 8 + g;
            bf[nt][0] = FU(Msm[n * 132 + ks + tg]);
            bf[nt][1] = FU(Msm[n * 132 + ks + tg + 4]);
        }
        #pragma unroll
        for (int mt = 0; mt < 4; mt++)
            #pragma unroll
            for (int nt = 0; nt < 4; nt++)
                mma_tf32(acc2[mt][nt], af[mt], bf[nt]);
    }

    #pragma unroll
    for (int mt = 0; mt < 4; mt++) {
        int c2 = wm * 64 + mt * 16 + g;
        #pragma unroll
        for (int nt = 0; nt < 4; nt++) {
            int e = wn * 32 + nt * 8 + tg * 2;
            float* c = acc2[mt][nt];
            *(float2*)(g_M2T + ((size_t)b * C_ + c2) * E_ + blk * 128 + e) =
                make_float2(tf32r(c[0]), tf32r(c[1]));
            *(float2*)(g_M2T + ((size_t)b * C_ + c2 + 8) * E_ + blk * 128 + e) =
                make_float2(tf32r(c[2]), tf32r(c[3]));
        }
    }
}

// ---------------- GEMM3: BM=128, MK both, STG=3, 2 CTAs/SM, full ldmatrix ----
#define T3 (128 * 36 * 4)          // 18432
#define DYN3 (3 * 2 * T3)          // 110592

__global__ __launch_bounds__(256, 2) void gemm3_kernel(const float* __restrict__ Hg,
                                                       const float* __restrict__ biasg,
                                                       float* __restrict__ Og) {
    extern __shared__ __align__(16) char ds[];
    __shared__ float scl[128];

    const int tid = threadIdx.x, b = blockIdx.z, blk = blockIdx.x;
    const int lane = tid & 31, wid = tid >> 5;
    const int g = lane >> 2, tg = lane & 3;
    const int wm = wid & 1, wn = wid >> 1;
    const int lm = ((lane >> 3) & 1) * 8 + (lane & 7);
    const int lk = (lane >> 4) * 4;

    const float* Ag = Hg + ((size_t)b * N_ + blk * 128) * E_;
    const float* Bg = g_M2T + (size_t)b * C_ * E_;

    if (tid < 128) scl[tid] = biasg[tid];

    const uint32_t sA = smem_u32(ds), sB = sA + 3 * T3;

    float acc[4][4][4];
    #pragma unroll
    for (int i = 0; i < 4; i++)
        #pragma unroll
        for (int j = 0; j < 4; j++)
            #pragma unroll
            for (int r = 0; r < 4; r++) acc[i][j][r] = 0.f;

    auto issue = [&](int kt) {
        int buf = kt - (kt / 3) * 3;
        #pragma unroll
        for (int i = 0; i < 4; i++) {
            int ch = tid + 256 * i;
            int m = ch >> 3, k4 = (ch & 7) * 4;
            CP16(sA + buf * T3 + (m * 36 + k4) * 4,
                 Ag + (size_t)m * E_ + kt * 32 + k4);
            CP16(sB + buf * T3 + (m * 36 + k4) * 4,
                 Bg + (size_t)m * E_ + kt * 32 + k4);
        }
        CP_COMMIT();
    };

    const int KT = E_ / 32;   // 64
    issue(0); issue(1);

    for (int kt = 0; kt < KT; kt++) {
        if (kt + 2 < KT) issue(kt + 2);
        int rem = KT - 1 - kt;
        if (rem >= 2)      CP_WAIT(2);
        else if (rem == 1) CP_WAIT(1);
        else               CP_WAIT(0);
        __syncthreads();

        int buf = kt - (kt / 3) * 3;
        float* As = (float*)(ds + (size_t)buf * T3);
        const uint32_t sAb = sA + (uint32_t)buf * T3;
        const uint32_t sBb = sB + (uint32_t)buf * T3;

        // ---- rounding pass on raw-H A tile (in place) ----
        {
            const int mb = tid >> 3, k4 = (tid & 7) * 4;
            #pragma unroll
            for (int i = 0; i < 4; i++) {
                float4 v = *(float4*)(As + (mb + 32 * i) * 36 + k4);
                v.x = tf32r(v.x); v.y = tf32r(v.y); v.z = tf32r(v.z); v.w = tf32r(v.w);
                *(float4*)(As + (mb + 32 * i) * 36 + k4) = v;
            }
        }
        __syncthreads();

        #pragma unroll
        for (int ks = 0; ks < 32; ks += 8) {
            uint32_t af[4][4], bf[4][2];
            #pragma unroll
            for (int mt = 0; mt < 4; mt++) {
                uint32_t addr = sAb + (uint32_t)(((wm * 64 + mt * 16 + lm) * 36 + ks + lk) * 4);
                LDSM4(af[mt][0], af[mt][1], af[mt][2], af[mt][3], addr);
            }
            #pragma unroll
            for (int p = 0; p < 2; p++) {
                uint32_t t0, t1, t2, t3;
                uint32_t addr = sBb + (uint32_t)(((wn * 32 + p * 16 + lm) * 36 + ks + lk) * 4);
                LDSM4(t0, t1, t2, t3, addr);
                bf[2 * p][0] = t0; bf[2 * p + 1][0] = t1;
                bf[2 * p][1] = t2; bf[2 * p + 1][1] = t3;
            }
            #pragma unroll
            for (int mt = 0; mt < 4; mt++)
                #pragma unroll
                for (int nt = 0; nt < 4; nt++)
                    mma_tf32(acc[mt][nt], af[mt], bf[nt]);
        }
        __syncthreads();
    }

    #pragma unroll
    for (int mt = 0; mt < 4; mt++) {
        int r = wm * 64 + mt * 16 + g;
        float s0 = g_DvInv[b * N_ + blk * 128 + r];
        float s1 = g_DvInv[b * N_ + blk * 128 + r + 8];
        #pragma unroll
        for (int nt = 0; nt < 4; nt++) {
            int col = wn * 32 + nt * 8 + tg * 2;
            float b0 = scl[col], b1 = scl[col + 1];
            float* c = acc[mt][nt];
            *(float2*)(Og + ((size_t)b * N_ + blk * 128 + r) * C_ + col) =
                make_float2(c[0] * s0 + b0, c[1] * s0 + b1);
            *(float2*)(Og + ((size_t)b * N_ + blk * 128 + r + 8) * C_ + col) =
                make_float2(c[2] * s1 + b0, c[3] * s1 + b1);
        }
    }
}

// ---------------- launch -----------------------------------------------------
extern "C" void kernel_launch(void* const* d_in, const int* in_sizes, int n_in,
                              void* d_out, int out_size) {
    const float *x = nullptr, *H = nullptr, *W = nullptr, *bias = nullptr;
    for (int i = 0; i < n_in; i++) {
        long long s = in_sizes[i];
        if (s == (long long)B_ * N_ * E_)      H = (const float*)d_in[i];
        else if (s == (long long)B_ * N_ * C_) x = (const float*)d_in[i];
        else if (s == (long long)C_ * C_)      W = (const float*)d_in[i];
        else if (s == (long long)C_)           bias = (const float*)d_in[i];
    }
    float* outp = (float*)d_out;

    cudaFuncSetAttribute(gemm1_kernel, cudaFuncAttributeMaxDynamicSharedMemorySize, DYN1);
    cudaFuncSetAttribute(gemm3_kernel, cudaFuncAttributeMaxDynamicSharedMemorySize, DYN3);

    dv_kernel<<<B_ * N_ / 8, dim3(32, 8)>>>(H);
    prep_xt<<<dim3(N_ / 32, C_ / 32, B_), dim3(32, 8)>>>(x);

    // M2T = W (De^-1 H^T (Dv^-1/2 x))^T   [gemm1 + fused De + fused linear]
    gemm1_kernel<<<dim3(E_ / 128, 1, B_), 256, DYN1>>>(H, W);
    // out = Dv^-1/2 (H M2) + bias
    gemm3_kernel<<<dim3(N_ / 128, 1, B_), 256, DYN3>>>(H, bias, outp);
}

// round 12
// speedup vs baseline: 1.1865x; 1.1865x over previous
#include <cuda_runtime.h>
#include <cstdint>

// BatchedHGNNLayer: out = diag(Dv^-1/2) H diag(De^-1) H^T diag(Dv^-1/2) x W^T + b
// B=8, N=4096, E=2048, C=128 fp32.
// gemm1: R9-proven (KM scalar frags, fused De + fused W M^T epilogue).
// gemm3: STG=3 2CTA/SM + ldmatrix frags, register-side rna on raw-H fragments.

#define B_ 8
#define N_ 4096
#define E_ 2048
#define C_ 128
#define EPS 1e-6f

// ---------------- scratch ----------------------------------------------------
__device__ float g_DvInv[B_ * N_];
__device__ float g_Xs[(size_t)B_ * N_ * C_];    // rna(x * DvInv)           [b][n][c]
__device__ float g_M2T[(size_t)B_ * C_ * E_];   // rna((De^-1 H^T Xs) W^T)^T [b][c2][e]

// ---------------- helpers ----------------------------------------------------
__device__ __forceinline__ float tf32r(float x) {
    uint32_t u;
    asm("cvt.rna.tf32.f32 %0, %1;" : "=r"(u) : "f"(x));
    return __uint_as_float(u);
}
__device__ __forceinline__ uint32_t tf32u(float x) {
    uint32_t u;
    asm("cvt.rna.tf32.f32 %0, %1;" : "=r"(u) : "f"(x));
    return u;
}
__device__ __forceinline__ uint32_t tf32uu(uint32_t x) {
    uint32_t u;
    asm("cvt.rna.tf32.f32 %0, %1;" : "=r"(u) : "f"(__uint_as_float(x)));
    return u;
}
__device__ __forceinline__ uint32_t smem_u32(const void* p) {
    uint32_t a;
    asm("{ .reg .u64 t; cvta.to.shared.u64 t, %1; cvt.u32.u64 %0, t; }" : "=r"(a) : "l"(p));
    return a;
}
__device__ __forceinline__ void mma_tf32(float* c, const uint32_t* a, const uint32_t* b) {
    asm volatile(
        "mma.sync.aligned.m16n8k8.row.col.f32.tf32.tf32.f32 "
        "{%0,%1,%2,%3}, {%4,%5,%6,%7}, {%8,%9}, {%0,%1,%2,%3};"
        : "+f"(c[0]), "+f"(c[1]), "+f"(c[2]), "+f"(c[3])
        : "r"(a[0]), "r"(a[1]), "r"(a[2]), "r"(a[3]), "r"(b[0]), "r"(b[1]));
}
#define CP16(dst, src) \
    asm volatile("cp.async.cg.shared.global [%0], [%1], 16;" :: "r"(dst), "l"(src))
#define CP_COMMIT() asm volatile("cp.async.commit_group;" ::: "memory")
#define CP_WAIT(n)  asm volatile("cp.async.wait_group %0;" :: "n"(n) : "memory")
#define FU(x) __float_as_uint(x)
#define LDSM4(r0, r1, r2, r3, addr)                                             \
    asm volatile("ldmatrix.sync.aligned.m8n8.x4.shared.b16 {%0,%1,%2,%3}, [%4];"\
                 : "=r"(r0), "=r"(r1), "=r"(r2), "=r"(r3) : "r"(addr))

// ---------------- small kernels ----------------------------------------------
__global__ void dv_kernel(const float* __restrict__ Hg) {
    int row = blockIdx.x * 8 + threadIdx.y;
    const float4* src = (const float4*)(Hg + (size_t)row * E_);
    float s = 0.f;
    for (int i = threadIdx.x; i < E_ / 4; i += 32) {
        float4 v = src[i];
        s += (v.x + v.y) + (v.z + v.w);
    }
    #pragma unroll
    for (int o = 16; o; o >>= 1) s += __shfl_xor_sync(0xffffffffu, s, o);
    if (threadIdx.x == 0) g_DvInv[row] = rsqrtf(s + EPS);
}

__global__ void prep_x(const float* __restrict__ xg) {
    int i = blockIdx.x * 256 + threadIdx.x;
    int row = i >> 5;
    float dv = g_DvInv[row];
    float4 v = ((const float4*)xg)[i];
    float4 r;
    r.x = tf32r(v.x * dv); r.y = tf32r(v.y * dv);
    r.z = tf32r(v.z * dv); r.w = tf32r(v.w * dv);
    ((float4*)g_Xs)[i] = r;
}

// ---------------- GEMM1 (+fused De, +fused W M^T): BM=128, KM layout ---------
#define T1 (32 * 136 * 4)          // 17408
#define DYN1 (8 * T1)              // 139264

__global__ __launch_bounds__(256, 1) void gemm1_kernel(const float* __restrict__ Hg,
                                                       const float* __restrict__ Wg) {
    extern __shared__ __align__(16) char ds[];
    __shared__ float deP[2][128];
    __shared__ float scl[128];

    const int tid = threadIdx.x, b = blockIdx.z, blk = blockIdx.x;
    const int lane = tid & 31, wid = tid >> 5;
    const int g = lane >> 2, tg = lane & 3;
    const int wm = wid & 1, wn = wid >> 1;

    const float* Ag = Hg + (size_t)b * N_ * E_;
    const float* Bg = g_Xs + (size_t)b * N_ * C_;
    const int acol = blk * 128;

    const uint32_t sA = smem_u32(ds), sB = sA + 4 * T1;

    float acc[4][4][4];
    #pragma unroll
    for (int i = 0; i < 4; i++)
        #pragma unroll
        for (int j = 0; j < 4; j++)
            #pragma unroll
            for (int r = 0; r < 4; r++) acc[i][j][r] = 0.f;

    float deacc = 0.f;
    const int mcol = tid & 127, half = tid >> 7;

    auto issue = [&](int kt) {
        int buf = kt & 3;
        #pragma unroll
        for (int i = 0; i < 4; i++) {
            int ch = tid + 256 * i;
            int k = ch >> 5, m4 = (ch & 31) * 4;
            CP16(sA + buf * T1 + (k * 136 + m4) * 4,
                 Ag + (size_t)(kt * 32 + k) * E_ + acol + m4);
            CP16(sB + buf * T1 + (k * 136 + m4) * 4,
                 Bg + (size_t)(kt * 32 + k) * C_ + m4);
        }
        CP_COMMIT();
    };

    const int KT = N_ / 32;   // 128
    issue(0); issue(1); issue(2);

    for (int kt = 0; kt < KT; kt++) {
        if (kt + 3 < KT) issue(kt + 3);
        int rem = KT - 1 - kt;
        if (rem >= 3)      CP_WAIT(3);
        else if (rem == 2) CP_WAIT(2);
        else if (rem == 1) CP_WAIT(1);
        else               CP_WAIT(0);
        __syncthreads();

        const float* As = (const float*)(ds + (size_t)(kt & 3) * T1);
        const float* Bs = (const float*)(ds + (size_t)4 * T1 + (size_t)(kt & 3) * T1);

        {   // fused De from RAW H
            float s = 0.f;
            #pragma unroll
            for (int k = 0; k < 16; k++) s += As[(half * 16 + k) * 136 + mcol];
            deacc += s;
        }

        #pragma unroll
        for (int ks = 0; ks < 32; ks += 8) {
            uint32_t af[4][4], bf[4][2];
            #pragma unroll
            for (int mt = 0; mt < 4; mt++) {
                int m = wm * 64 + mt * 16 + g;
                af[mt][0] = tf32u(As[(ks + tg) * 136 + m]);
                af[mt][1] = tf32u(As[(ks + tg) * 136 + m + 8]);
                af[mt][2] = tf32u(As[(ks + tg + 4) * 136 + m]);
                af[mt][3] = tf32u(As[(ks + tg + 4) * 136 + m + 8]);
            }
            #pragma unroll
            for (int nt = 0; nt < 4; nt++) {
                int n = wn * 32 + nt * 8 + g;
                bf[nt][0] = FU(Bs[(ks + tg) * 136 + n]);
                bf[nt][1] = FU(Bs[(ks + tg + 4) * 136 + n]);
            }
            #pragma unroll
            for (int mt = 0; mt < 4; mt++)
                #pragma unroll
                for (int nt = 0; nt < 4; nt++)
                    mma_tf32(acc[mt][nt], af[mt], bf[nt]);
        }
        __syncthreads();
    }

    // ---- epilogue: W load + De + in-CTA sub-GEMM M2T = W M^T ----
    float* Msm = (float*)ds;                     // [128][132]
    float* Wsm = (float*)(ds + 4 * T1);          // [128][132]
    {
        const uint32_t sW = smem_u32(Wsm);
        #pragma unroll
        for (int i = 0; i < 16; i++) {
            int ch = tid + 256 * i;              // 4096 chunks: 128 x 32
            int m = ch >> 5, q = ch & 31;
            CP16(sW + (m * 132 + q * 4) * 4, Wg + (size_t)m * C_ + q * 4);
        }
        CP_COMMIT();
    }
    deP[half][mcol] = deacc;
    __syncthreads();
    if (tid < 128) scl[tid] = 1.0f / (deP[0][tid] + deP[1][tid] + EPS);
    __syncthreads();

    #pragma unroll
    for (int mt = 0; mt < 4; mt++) {
        int r = wm * 64 + mt * 16 + g;
        float s0 = scl[r], s1 = scl[r + 8];
        #pragma unroll
        for (int nt = 0; nt < 4; nt++) {
            int col = wn * 32 + nt * 8 + tg * 2;
            float* c = acc[mt][nt];
            *(float2*)(Msm + r * 132 + col) =
                make_float2(tf32r(c[0] * s0), tf32r(c[1] * s0));
            *(float2*)(Msm + (r + 8) * 132 + col) =
                make_float2(tf32r(c[2] * s1), tf32r(c[3] * s1));
        }
    }
    CP_WAIT(0);
    __syncthreads();

    float acc2[4][4][4];
    #pragma unroll
    for (int i = 0; i < 4; i++)
        #pragma unroll
        for (int j = 0; j < 4; j++)
            #pragma unroll
            for (int r = 0; r < 4; r++) acc2[i][j][r] = 0.f;

    for (int ks = 0; ks < 128; ks += 8) {
        uint32_t af[4][4], bf[4][2];
        #pragma unroll
        for (int mt = 0; mt < 4; mt++) {
            int m = wm * 64 + mt * 16 + g;
            af[mt][0] = tf32u(Wsm[m * 132 + ks + tg]);
            af[mt][1] = tf32u(Wsm[(m + 8) * 132 + ks + tg]);
            af[mt][2] = tf32u(Wsm[m * 132 + ks + tg + 4]);
            af[mt][3] = tf32u(Wsm[(m + 8) * 132 + ks + tg + 4]);
        }
        #pragma unroll
        for (int nt = 0; nt < 4; nt++) {
            int n = wn * 32 + nt * 8 + g;
            bf[nt][0] = FU(Msm[n * 132 + ks + tg]);
            bf[nt][1] = FU(Msm[n * 132 + ks + tg + 4]);
        }
        #pragma unroll
        for (int mt = 0; mt < 4; mt++)
            #pragma unroll
            for (int nt = 0; nt < 4; nt++)
                mma_tf32(acc2[mt][nt], af[mt], bf[nt]);
    }

    #pragma unroll
    for (int mt = 0; mt < 4; mt++) {
        int c2 = wm * 64 + mt * 16 + g;
        #pragma unroll
        for (int nt = 0; nt < 4; nt++) {
            int e = wn * 32 + nt * 8 + tg * 2;
            float* c = acc2[mt][nt];
            *(float2*)(g_M2T + ((size_t)b * C_ + c2) * E_ + blk * 128 + e) =
                make_float2(tf32r(c[0]), tf32r(c[1]));
            *(float2*)(g_M2T + ((size_t)b * C_ + c2 + 8) * E_ + blk * 128 + e) =
                make_float2(tf32r(c[2]), tf32r(c[3]));
        }
    }
}

// ---------------- GEMM3: MK both, STG=3, 2 CTAs/SM, ldmatrix frags -----------
#define T3 (128 * 36 * 4)          // 18432
#define DYN3 (3 * 2 * T3)          // 110592

__global__ __launch_bounds__(256, 2) void gemm3_kernel(const float* __restrict__ Hg,
                                                       const float* __restrict__ biasg,
                                                       float* __restrict__ Og) {
    extern __shared__ __align__(16) char ds[];
    __shared__ float scl[128];

    const int tid = threadIdx.x, b = blockIdx.z, blk = blockIdx.x;
    const int lane = tid & 31, wid = tid >> 5;
    const int g = lane >> 2, tg = lane & 3;
    const int wm = wid & 1, wn = wid >> 1;
    const int lm = ((lane >> 3) & 1) * 8 + (lane & 7);   // ldmatrix row component
    const int lk = (lane >> 4) * 4;                      // ldmatrix col component

    const float* Ag = Hg + ((size_t)b * N_ + blk * 128) * E_;
    const float* Bg = g_M2T + (size_t)b * C_ * E_;

    if (tid < 128) scl[tid] = biasg[tid];

    const uint32_t sA = smem_u32(ds), sB = sA + 3 * T3;

    float acc[4][4][4];
    #pragma unroll
    for (int i = 0; i < 4; i++)
        #pragma unroll
        for (int j = 0; j < 4; j++)
            #pragma unroll
            for (int r = 0; r < 4; r++) acc[i][j][r] = 0.f;

    auto issue = [&](int kt) {
        int buf = kt - (kt / 3) * 3;
        #pragma unroll
        for (int i = 0; i < 4; i++) {
            int ch = tid + 256 * i;
            int m = ch >> 3, k4 = (ch & 7) * 4;
            CP16(sA + buf * T3 + (m * 36 + k4) * 4,
                 Ag + (size_t)m * E_ + kt * 32 + k4);
            CP16(sB + buf * T3 + (m * 36 + k4) * 4,
                 Bg + (size_t)m * E_ + kt * 32 + k4);
        }
        CP_COMMIT();
    };

    const int KT = E_ / 32;   // 64
    issue(0); issue(1);

    for (int kt = 0; kt < KT; kt++) {
        if (kt + 2 < KT) issue(kt + 2);
        int rem = KT - 1 - kt;
        if (rem >= 2)      CP_WAIT(2);
        else if (rem == 1) CP_WAIT(1);
        else               CP_WAIT(0);
        __syncthreads();

        int buf = kt - (kt / 3) * 3;
        const uint32_t sAb = sA + (uint32_t)buf * T3;
        const uint32_t sBb = sB + (uint32_t)buf * T3;

        #pragma unroll
        for (int ks = 0; ks < 32; ks += 8) {
            uint32_t af[4][4], bf[4][2];
            #pragma unroll
            for (int mt = 0; mt < 4; mt++) {
                uint32_t addr = sAb + (uint32_t)(((wm * 64 + mt * 16 + lm) * 36 + ks + lk) * 4);
                LDSM4(af[mt][0], af[mt][1], af[mt][2], af[mt][3], addr);
                af[mt][0] = tf32uu(af[mt][0]);   // raw H -> rna in registers
                af[mt][1] = tf32uu(af[mt][1]);
                af[mt][2] = tf32uu(af[mt][2]);
                af[mt][3] = tf32uu(af[mt][3]);
            }
            #pragma unroll
            for (int p = 0; p < 2; p++) {
                uint32_t t0, t1, t2, t3;
                uint32_t addr = sBb + (uint32_t)(((wn * 32 + p * 16 + lm) * 36 + ks + lk) * 4);
                LDSM4(t0, t1, t2, t3, addr);   // B pre-rounded -> no cvt
                bf[2 * p][0] = t0; bf[2 * p + 1][0] = t1;
                bf[2 * p][1] = t2; bf[2 * p + 1][1] = t3;
            }
            #pragma unroll
            for (int mt = 0; mt < 4; mt++)
                #pragma unroll
                for (int nt = 0; nt < 4; nt++)
                    mma_tf32(acc[mt][nt], af[mt], bf[nt]);
        }
        __syncthreads();
    }

    #pragma unroll
    for (int mt = 0; mt < 4; mt++) {
        int r = wm * 64 + mt * 16 + g;
        float s0 = g_DvInv[b * N_ + blk * 128 + r];
        float s1 = g_DvInv[b * N_ + blk * 128 + r + 8];
        #pragma unroll
        for (int nt = 0; nt < 4; nt++) {
            int col = wn * 32 + nt * 8 + tg * 2;
            float b0 = scl[col], b1 = scl[col + 1];
            float* c = acc[mt][nt];
            *(float2*)(Og + ((size_t)b * N_ + blk * 128 + r) * C_ + col) =
                make_float2(c[0] * s0 + b0, c[1] * s0 + b1);
            *(float2*)(Og + ((size_t)b * N_ + blk * 128 + r + 8) * C_ + col) =
                make_float2(c[2] * s1 + b0, c[3] * s1 + b1);
        }
    }
}

// ---------------- launch -----------------------------------------------------
extern "C" void kernel_launch(void* const* d_in, const int* in_sizes, int n_in,
                              void* d_out, int out_size) {
    const float *x = nullptr, *H = nullptr, *W = nullptr, *bias = nullptr;
    for (int i = 0; i < n_in; i++) {
        long long s = in_sizes[i];
        if (s == (long long)B_ * N_ * E_)      H = (const float*)d_in[i];
        else if (s == (long long)B_ * N_ * C_) x = (const float*)d_in[i];
        else if (s == (long long)C_ * C_)      W = (const float*)d_in[i];
        else if (s == (long long)C_)           bias = (const float*)d_in[i];
    }
    float* outp = (float*)d_out;

    cudaFuncSetAttribute(gemm1_kernel, cudaFuncAttributeMaxDynamicSharedMemorySize, DYN1);
    cudaFuncSetAttribute(gemm3_kernel, cudaFuncAttributeMaxDynamicSharedMemorySize, DYN3);

    dv_kernel<<<B_ * N_ / 8, dim3(32, 8)>>>(H);
    prep_x<<<(B_ * N_ * C_ / 4) / 256, 256>>>(x);

    // M2T = W (De^-1 H^T (Dv^-1/2 x))^T   [gemm1 + fused De + fused linear]
    gemm1_kernel<<<dim3(E_ / 128, 1, B_), 256, DYN1>>>(H, W);
    // out = Dv^-1/2 (H M2) + bias
    gemm3_kernel<<<dim3(N_ / 128, 1, B_), 256, DYN3>>>(H, bias, outp);
}

// round 13
// speedup vs baseline: 1.2134x; 1.0227x over previous
#include <cuda_runtime.h>
#include <cstdint>

// BatchedHGNNLayer: out = diag(Dv^-1/2) H diag(De^-1) H^T diag(Dv^-1/2) x W^T + b
// B=8, N=4096, E=2048, C=128 fp32.
// R12 + single-__syncthreads pipelines + epilogue W-load race fix.

#define B_ 8
#define N_ 4096
#define E_ 2048
#define C_ 128
#define EPS 1e-6f

// ---------------- scratch ----------------------------------------------------
__device__ float g_DvInv[B_ * N_];
__device__ float g_Xs[(size_t)B_ * N_ * C_];    // rna(x * DvInv)           [b][n][c]
__device__ float g_M2T[(size_t)B_ * C_ * E_];   // rna((De^-1 H^T Xs) W^T)^T [b][c2][e]

// ---------------- helpers ----------------------------------------------------
__device__ __forceinline__ float tf32r(float x) {
    uint32_t u;
    asm("cvt.rna.tf32.f32 %0, %1;" : "=r"(u) : "f"(x));
    return __uint_as_float(u);
}
__device__ __forceinline__ uint32_t tf32u(float x) {
    uint32_t u;
    asm("cvt.rna.tf32.f32 %0, %1;" : "=r"(u) : "f"(x));
    return u;
}
__device__ __forceinline__ uint32_t tf32uu(uint32_t x) {
    uint32_t u;
    asm("cvt.rna.tf32.f32 %0, %1;" : "=r"(u) : "f"(__uint_as_float(x)));
    return u;
}
__device__ __forceinline__ uint32_t smem_u32(const void* p) {
    uint32_t a;
    asm("{ .reg .u64 t; cvta.to.shared.u64 t, %1; cvt.u32.u64 %0, t; }" : "=r"(a) : "l"(p));
    return a;
}
__device__ __forceinline__ void mma_tf32(float* c, const uint32_t* a, const uint32_t* b) {
    asm volatile(
        "mma.sync.aligned.m16n8k8.row.col.f32.tf32.tf32.f32 "
        "{%0,%1,%2,%3}, {%4,%5,%6,%7}, {%8,%9}, {%0,%1,%2,%3};"
        : "+f"(c[0]), "+f"(c[1]), "+f"(c[2]), "+f"(c[3])
        : "r"(a[0]), "r"(a[1]), "r"(a[2]), "r"(a[3]), "r"(b[0]), "r"(b[1]));
}
#define CP16(dst, src) \
    asm volatile("cp.async.cg.shared.global [%0], [%1], 16;" :: "r"(dst), "l"(src))
#define CP_COMMIT() asm volatile("cp.async.commit_group;" ::: "memory")
#define CP_WAIT(n)  asm volatile("cp.async.wait_group %0;" :: "n"(n) : "memory")
#define FU(x) __float_as_uint(x)
#define LDSM4(r0, r1, r2, r3, addr)                                             \
    asm volatile("ldmatrix.sync.aligned.m8n8.x4.shared.b16 {%0,%1,%2,%3}, [%4];"\
                 : "=r"(r0), "=r"(r1), "=r"(r2), "=r"(r3) : "r"(addr))

// ---------------- small kernels ----------------------------------------------
__global__ void dv_kernel(const float* __restrict__ Hg) {
    int row = blockIdx.x * 8 + threadIdx.y;
    const float4* src = (const float4*)(Hg + (size_t)row * E_);
    float s = 0.f;
    for (int i = threadIdx.x; i < E_ / 4; i += 32) {
        float4 v = src[i];
        s += (v.x + v.y) + (v.z + v.w);
    }
    #pragma unroll
    for (int o = 16; o; o >>= 1) s += __shfl_xor_sync(0xffffffffu, s, o);
    if (threadIdx.x == 0) g_DvInv[row] = rsqrtf(s + EPS);
}

__global__ void prep_x(const float* __restrict__ xg) {
    int i = blockIdx.x * 256 + threadIdx.x;
    int row = i >> 5;
    float dv = g_DvInv[row];
    float4 v = ((const float4*)xg)[i];
    float4 r;
    r.x = tf32r(v.x * dv); r.y = tf32r(v.y * dv);
    r.z = tf32r(v.z * dv); r.w = tf32r(v.w * dv);
    ((float4*)g_Xs)[i] = r;
}

// ---------------- GEMM1 (+fused De, +fused W M^T): BM=128, KM layout ---------
#define T1 (32 * 136 * 4)          // 17408
#define DYN1 (8 * T1)              // 139264

__global__ __launch_bounds__(256, 1) void gemm1_kernel(const float* __restrict__ Hg,
                                                       const float* __restrict__ Wg) {
    extern __shared__ __align__(16) char ds[];
    __shared__ float deP[2][128];
    __shared__ float scl[128];

    const int tid = threadIdx.x, b = blockIdx.z, blk = blockIdx.x;
    const int lane = tid & 31, wid = tid >> 5;
    const int g = lane >> 2, tg = lane & 3;
    const int wm = wid & 1, wn = wid >> 1;

    const float* Ag = Hg + (size_t)b * N_ * E_;
    const float* Bg = g_Xs + (size_t)b * N_ * C_;
    const int acol = blk * 128;

    const uint32_t sA = smem_u32(ds), sB = sA + 4 * T1;

    float acc[4][4][4];
    #pragma unroll
    for (int i = 0; i < 4; i++)
        #pragma unroll
        for (int j = 0; j < 4; j++)
            #pragma unroll
            for (int r = 0; r < 4; r++) acc[i][j][r] = 0.f;

    float deacc = 0.f;
    const int mcol = tid & 127, half = tid >> 7;

    auto issue = [&](int kt) {
        int buf = kt & 3;
        #pragma unroll
        for (int i = 0; i < 4; i++) {
            int ch = tid + 256 * i;
            int k = ch >> 5, m4 = (ch & 31) * 4;
            CP16(sA + buf * T1 + (k * 136 + m4) * 4,
                 Ag + (size_t)(kt * 32 + k) * E_ + acol + m4);
            CP16(sB + buf * T1 + (k * 136 + m4) * 4,
                 Bg + (size_t)(kt * 32 + k) * C_ + m4);
        }
        CP_COMMIT();
    };

    const int KT = N_ / 32;   // 128
    issue(0); issue(1); issue(2);

    for (int kt = 0; kt < KT; kt++) {
        int rem = KT - 1 - kt;          // groups pending beyond kt once issues stop
        if (rem >= 2)      CP_WAIT(2);
        else if (rem == 1) CP_WAIT(1);
        else               CP_WAIT(0);
        __syncthreads();                // single barrier per kt

        const float* As = (const float*)(ds + (size_t)(kt & 3) * T1);
        const float* Bs = (const float*)(ds + (size_t)4 * T1 + (size_t)(kt & 3) * T1);

        {   // fused De from RAW H
            float s = 0.f;
            #pragma unroll
            for (int k = 0; k < 16; k++) s += As[(half * 16 + k) * 136 + mcol];
            deacc += s;
        }

        #pragma unroll
        for (int ks = 0; ks < 32; ks += 8) {
            uint32_t af[4][4], bf[4][2];
            #pragma unroll
            for (int mt = 0; mt < 4; mt++) {
                int m = wm * 64 + mt * 16 + g;
                af[mt][0] = tf32u(As[(ks + tg) * 136 + m]);
                af[mt][1] = tf32u(As[(ks + tg) * 136 + m + 8]);
                af[mt][2] = tf32u(As[(ks + tg + 4) * 136 + m]);
                af[mt][3] = tf32u(As[(ks + tg + 4) * 136 + m + 8]);
            }
            #pragma unroll
            for (int nt = 0; nt < 4; nt++) {
                int n = wn * 32 + nt * 8 + g;
                bf[nt][0] = FU(Bs[(ks + tg) * 136 + n]);
                bf[nt][1] = FU(Bs[(ks + tg + 4) * 136 + n]);
            }
            #pragma unroll
            for (int mt = 0; mt < 4; mt++)
                #pragma unroll
                for (int nt = 0; nt < 4; nt++)
                    mma_tf32(acc[mt][nt], af[mt], bf[nt]);
        }

        if (kt + 3 < KT) issue(kt + 3); // safe: all threads past top sync => done with buf (kt-1)&3
    }

    // ---- epilogue ----
    float* Msm = (float*)ds;                     // [128][132]
    float* Wsm = (float*)(ds + 4 * T1);          // [128][132]

    deP[half][mcol] = deacc;
    __syncthreads();                             // ALL compute done -> B-ring reusable
    {
        const uint32_t sW = smem_u32(Wsm);
        #pragma unroll
        for (int i = 0; i < 16; i++) {
            int ch = tid + 256 * i;              // 4096 chunks: 128 x 32
            int m = ch >> 5, q = ch & 31;
            CP16(sW + (m * 132 + q * 4) * 4, Wg + (size_t)m * C_ + q * 4);
        }
        CP_COMMIT();
    }
    if (tid < 128) scl[tid] = 1.0f / (deP[0][tid] + deP[1][tid] + EPS);
    __syncthreads();

    #pragma unroll
    for (int mt = 0; mt < 4; mt++) {
        int r = wm * 64 + mt * 16 + g;
        float s0 = scl[r], s1 = scl[r + 8];
        #pragma unroll
        for (int nt = 0; nt < 4; nt++) {
            int col = wn * 32 + nt * 8 + tg * 2;
            float* c = acc[mt][nt];
            *(float2*)(Msm + r * 132 + col) =
                make_float2(tf32r(c[0] * s0), tf32r(c[1] * s0));
            *(float2*)(Msm + (r + 8) * 132 + col) =
                make_float2(tf32r(c[2] * s1), tf32r(c[3] * s1));
        }
    }
    CP_WAIT(0);
    __syncthreads();

    float acc2[4][4][4];
    #pragma unroll
    for (int i = 0; i < 4; i++)
        #pragma unroll
        for (int j = 0; j < 4; j++)
            #pragma unroll
            for (int r = 0; r < 4; r++) acc2[i][j][r] = 0.f;

    for (int ks = 0; ks < 128; ks += 8) {
        uint32_t af[4][4], bf[4][2];
        #pragma unroll
        for (int mt = 0; mt < 4; mt++) {
            int m = wm * 64 + mt * 16 + g;
            af[mt][0] = tf32u(Wsm[m * 132 + ks + tg]);
            af[mt][1] = tf32u(Wsm[(m + 8) * 132 + ks + tg]);
            af[mt][2] = tf32u(Wsm[m * 132 + ks + tg + 4]);
            af[mt][3] = tf32u(Wsm[(m + 8) * 132 + ks + tg + 4]);
        }
        #pragma unroll
        for (int nt = 0; nt < 4; nt++) {
            int n = wn * 32 + nt * 8 + g;
            bf[nt][0] = FU(Msm[n * 132 + ks + tg]);
            bf[nt][1] = FU(Msm[n * 132 + ks + tg + 4]);
        }
        #pragma unroll
        for (int mt = 0; mt < 4; mt++)
            #pragma unroll
            for (int nt = 0; nt < 4; nt++)
                mma_tf32(acc2[mt][nt], af[mt], bf[nt]);
    }

    #pragma unroll
    for (int mt = 0; mt < 4; mt++) {
        int c2 = wm * 64 + mt * 16 + g;
        #pragma unroll
        for (int nt = 0; nt < 4; nt++) {
            int e = wn * 32 + nt * 8 + tg * 2;
            float* c = acc2[mt][nt];
            *(float2*)(g_M2T + ((size_t)b * C_ + c2) * E_ + blk * 128 + e) =
                make_float2(tf32r(c[0]), tf32r(c[1]));
            *(float2*)(g_M2T + ((size_t)b * C_ + c2 + 8) * E_ + blk * 128 + e) =
                make_float2(tf32r(c[2]), tf32r(c[3]));
        }
    }
}

// ---------------- GEMM3: MK both, STG=3, 2 CTAs/SM, ldmatrix frags -----------
#define T3 (128 * 36 * 4)          // 18432
#define DYN3 (3 * 2 * T3)          // 110592

__global__ __launch_bounds__(256, 2) void gemm3_kernel(const float* __restrict__ Hg,
                                                       const float* __restrict__ biasg,
                                                       float* __restrict__ Og) {
    extern __shared__ __align__(16) char ds[];
    __shared__ float scl[128];

    const int tid = threadIdx.x, b = blockIdx.z, blk = blockIdx.x;
    const int lane = tid & 31, wid = tid >> 5;
    const int g = lane >> 2, tg = lane & 3;
    const int wm = wid & 1, wn = wid >> 1;
    const int lm = ((lane >> 3) & 1) * 8 + (lane & 7);
    const int lk = (lane >> 4) * 4;

    const float* Ag = Hg + ((size_t)b * N_ + blk * 128) * E_;
    const float* Bg = g_M2T + (size_t)b * C_ * E_;

    if (tid < 128) scl[tid] = biasg[tid];

    const uint32_t sA = smem_u32(ds), sB = sA + 3 * T3;

    float acc[4][4][4];
    #pragma unroll
    for (int i = 0; i < 4; i++)
        #pragma unroll
        for (int j = 0; j < 4; j++)
            #pragma unroll
            for (int r = 0; r < 4; r++) acc[i][j][r] = 0.f;

    auto issue = [&](int kt, int buf) {
        #pragma unroll
        for (int i = 0; i < 4; i++) {
            int ch = tid + 256 * i;
            int m = ch >> 3, k4 = (ch & 7) * 4;
            CP16(sA + buf * T3 + (m * 36 + k4) * 4,
                 Ag + (size_t)m * E_ + kt * 32 + k4);
            CP16(sB + buf * T3 + (m * 36 + k4) * 4,
                 Bg + (size_t)m * E_ + kt * 32 + k4);
        }
        CP_COMMIT();
    };

    const int KT = E_ / 32;   // 64
    issue(0, 0); issue(1, 1);

    int cbuf = 0, ibuf = 2;
    for (int kt = 0; kt < KT; kt++) {
        int rem = KT - 1 - kt;
        if (rem >= 1) CP_WAIT(1);
        else          CP_WAIT(0);
        __syncthreads();                // single barrier per kt

        const uint32_t sAb = sA + (uint32_t)cbuf * T3;
        const uint32_t sBb = sB + (uint32_t)cbuf * T3;

        #pragma unroll
        for (int ks = 0; ks < 32; ks += 8) {
            uint32_t af[4][4], bf[4][2];
            #pragma unroll
            for (int mt = 0; mt < 4; mt++) {
                uint32_t addr = sAb + (uint32_t)(((wm * 64 + mt * 16 + lm) * 36 + ks + lk) * 4);
                LDSM4(af[mt][0], af[mt][1], af[mt][2], af[mt][3], addr);
                af[mt][0] = tf32uu(af[mt][0]);
                af[mt][1] = tf32uu(af[mt][1]);
                af[mt][2] = tf32uu(af[mt][2]);
                af[mt][3] = tf32uu(af[mt][3]);
            }
            #pragma unroll
            for (int p = 0; p < 2; p++) {
                uint32_t t0, t1, t2, t3;
                uint32_t addr = sBb + (uint32_t)(((wn * 32 + p * 16 + lm) * 36 + ks + lk) * 4);
                LDSM4(t0, t1, t2, t3, addr);
                bf[2 * p][0] = t0; bf[2 * p + 1][0] = t1;
                bf[2 * p][1] = t2; bf[2 * p + 1][1] = t3;
            }
            #pragma unroll
            for (int mt = 0; mt < 4; mt++)
                #pragma unroll
                for (int nt = 0; nt < 4; nt++)
                    mma_tf32(acc[mt][nt], af[mt], bf[nt]);
        }

        if (kt + 2 < KT) issue(kt + 2, ibuf);   // safe: all past top sync of kt
        cbuf = (cbuf == 2) ? 0 : cbuf + 1;
        ibuf = (ibuf == 2) ? 0 : ibuf + 1;
    }

    #pragma unroll
    for (int mt = 0; mt < 4; mt++) {
        int r = wm * 64 + mt * 16 + g;
        float s0 = g_DvInv[b * N_ + blk * 128 + r];
        float s1 = g_DvInv[b * N_ + blk * 128 + r + 8];
        #pragma unroll
        for (int nt = 0; nt < 4; nt++) {
            int col = wn * 32 + nt * 8 + tg * 2;
            float b0 = scl[col], b1 = scl[col + 1];
            float* c = acc[mt][nt];
            *(float2*)(Og + ((size_t)b * N_ + blk * 128 + r) * C_ + col) =
                make_float2(c[0] * s0 + b0, c[1] * s0 + b1);
            *(float2*)(Og + ((size_t)b * N_ + blk * 128 + r + 8) * C_ + col) =
                make_float2(c[2] * s1 + b0, c[3] * s1 + b1);
        }
    }
}

// ---------------- launch -----------------------------------------------------
extern "C" void kernel_launch(void* const* d_in, const int* in_sizes, int n_in,
                              void* d_out, int out_size) {
    const float *x = nullptr, *H = nullptr, *W = nullptr, *bias = nullptr;
    for (int i = 0; i < n_in; i++) {
        long long s = in_sizes[i];
        if (s == (long long)B_ * N_ * E_)      H = (const float*)d_in[i];
        else if (s == (long long)B_ * N_ * C_) x = (const float*)d_in[i];
        else if (s == (long long)C_ * C_)      W = (const float*)d_in[i];
        else if (s == (long long)C_)           bias = (const float*)d_in[i];
    }
    float* outp = (float*)d_out;

    cudaFuncSetAttribute(gemm1_kernel, cudaFuncAttributeMaxDynamicSharedMemorySize, DYN1);
    cudaFuncSetAttribute(gemm3_kernel, cudaFuncAttributeMaxDynamicSharedMemorySize, DYN3);

    dv_kernel<<<B_ * N_ / 8, dim3(32, 8)>>>(H);
    prep_x<<<(B_ * N_ * C_ / 4) / 256, 256>>>(x);

    // M2T = W (De^-1 H^T (Dv^-1/2 x))^T   [gemm1 + fused De + fused linear]
    gemm1_kernel<<<dim3(E_ / 128, 1, B_), 256, DYN1>>>(H, W);
    // out = Dv^-1/2 (H M2) + bias
    gemm3_kernel<<<dim3(N_ / 128, 1, B_), 256, DYN3>>>(H, bias, outp);
}

// round 14
// speedup vs baseline: 1.7211x; 1.4184x over previous
#include <cuda_runtime.h>
#include <cuda_fp16.h>
#include <cstdint>

// BatchedHGNNLayer: out = diag(Dv^-1/2) H diag(De^-1) H^T diag(Dv^-1/2) x W^T + b
// B=8, N=4096, E=2048, C=128 fp32 in/out.
// FP16 operand pipeline (same 10-bit mantissa as tf32), m16n8k16 HMMA,
// ldmatrix(.trans) fragments, cp.async rings, fused De + fused linear.

#define B_ 8
#define N_ 4096
#define E_ 2048
#define C_ 128
#define EPS 1e-6f

// ---------------- scratch ----------------------------------------------------
__device__ float  g_DvInv[B_ * N_];
__device__ __half g_Hh[(size_t)B_ * N_ * E_];     // fp16(H)            [b][n][e]
__device__ __half g_Xh[(size_t)B_ * N_ * C_];     // fp16(x * DvInv)    [b][n][c]
__device__ __half g_Wh[C_ * C_];                  // fp16(W)
__device__ __half g_M2Th[(size_t)B_ * C_ * E_];   // fp16((De^-1 H^T Xs) W^T)^T [b][c2][e]

// ---------------- helpers ----------------------------------------------------
__device__ __forceinline__ uint32_t smem_u32(const void* p) {
    uint32_t a;
    asm("{ .reg .u64 t; cvta.to.shared.u64 t, %1; cvt.u32.u64 %0, t; }" : "=r"(a) : "l"(p));
    return a;
}
__device__ __forceinline__ uint32_t h2u(float a, float b) {
    __half2 h = __floats2half2_rn(a, b);
    return *(uint32_t*)&h;
}
__device__ __forceinline__ void mma_f16(float* c, const uint32_t* a, const uint32_t* b) {
    asm volatile(
        "mma.sync.aligned.m16n8k16.row.col.f32.f16.f16.f32 "
        "{%0,%1,%2,%3}, {%4,%5,%6,%7}, {%8,%9}, {%0,%1,%2,%3};"
        : "+f"(c[0]), "+f"(c[1]), "+f"(c[2]), "+f"(c[3])
        : "r"(a[0]), "r"(a[1]), "r"(a[2]), "r"(a[3]), "r"(b[0]), "r"(b[1]));
}
#define CP16(dst, src) \
    asm volatile("cp.async.cg.shared.global [%0], [%1], 16;" :: "r"(dst), "l"(src))
#define CP_COMMIT() asm volatile("cp.async.commit_group;" ::: "memory")
#define CP_WAIT(n)  asm volatile("cp.async.wait_group %0;" :: "n"(n) : "memory")
#define LDSM4(r0, r1, r2, r3, addr)                                             \
    asm volatile("ldmatrix.sync.aligned.m8n8.x4.shared.b16 {%0,%1,%2,%3}, [%4];"\
                 : "=r"(r0), "=r"(r1), "=r"(r2), "=r"(r3) : "r"(addr))
#define LDSM4T(r0, r1, r2, r3, addr)                                            \
    asm volatile("ldmatrix.sync.aligned.m8n8.x4.trans.shared.b16 {%0,%1,%2,%3}, [%4];"\
                 : "=r"(r0), "=r"(r1), "=r"(r2), "=r"(r3) : "r"(addr))

// ---------------- prep kernels -------------------------------------------------
// H -> fp16 copy + Dv row sums (raw f32, matches reference)
__global__ void prep_h(const float* __restrict__ Hg) {
    int row = blockIdx.x * 8 + threadIdx.y;
    const float4* src = (const float4*)(Hg + (size_t)row * E_);
    uint2* dst = (uint2*)(g_Hh + (size_t)row * E_);
    float s = 0.f;
    for (int i = threadIdx.x; i < E_ / 4; i += 32) {
        float4 v = src[i];
        s += (v.x + v.y) + (v.z + v.w);
        uint2 u; u.x = h2u(v.x, v.y); u.y = h2u(v.z, v.w);
        dst[i] = u;
    }
    #pragma unroll
    for (int o = 16; o; o >>= 1) s += __shfl_xor_sync(0xffffffffu, s, o);
    if (threadIdx.x == 0) g_DvInv[row] = rsqrtf(s + EPS);
}

__global__ void prep_x(const float* __restrict__ xg) {
    int i = blockIdx.x * 256 + threadIdx.x;     // f4 index
    int row = i >> 5;
    float dv = g_DvInv[row];
    float4 v = ((const float4*)xg)[i];
    uint2 u; u.x = h2u(v.x * dv, v.y * dv); u.y = h2u(v.z * dv, v.w * dv);
    ((uint2*)g_Xh)[i] = u;
}

__global__ void prep_w(const float* __restrict__ Wg) {
    int i = blockIdx.x * 256 + threadIdx.x;     // 4096 f4
    float4 v = ((const float4*)Wg)[i];
    uint2 u; u.x = h2u(v.x, v.y); u.y = h2u(v.z, v.w);
    ((uint2*)g_Wh)[i] = u;
}

// ---------------- GEMM1 (+fused De, +fused W M^T): BM=128, [k][m] fp16 -------
#define T1H (32 * 136 * 2)         // 8704 bytes per tile
#define DYN1 (8 * T1H)             // 69632

__global__ __launch_bounds__(256, 1) void gemm1_kernel() {
    extern __shared__ __align__(16) char ds[];
    __shared__ float deP[2][128];
    __shared__ float scl[128];

    const int tid = threadIdx.x, b = blockIdx.z, blk = blockIdx.x;
    const int lane = tid & 31, wid = tid >> 5;
    const int g = lane >> 2, tg = lane & 3;
    const int wm = wid & 1, wn = wid >> 1;
    // LDSM quad decomposition: r = row-in-octet, q0 -> +8 in m/n, q1 -> +8 in k
    const int r8 = lane & 7, q0 = (lane >> 3) & 1, q1 = (lane >> 4) & 1;

    const __half* Ag = g_Hh + (size_t)b * N_ * E_;
    const __half* Bg = g_Xh + (size_t)b * N_ * C_;
    const int acol = blk * 128;

    const uint32_t sA = smem_u32(ds), sB = sA + 4 * T1H;
    // trans-LDSM per-lane offsets in [k][x] tiles (stride 136 halfs)
    const uint32_t offT = (uint32_t)(((q1 * 8 + r8) * 136 + q0 * 8) * 2);

    float acc[4][4][4];
    #pragma unroll
    for (int i = 0; i < 4; i++)
        #pragma unroll
        for (int j = 0; j < 4; j++)
            #pragma unroll
            for (int rr = 0; rr < 4; rr++) acc[i][j][rr] = 0.f;

    float deacc = 0.f;
    const int mcol = tid & 127, half = tid >> 7;

    auto issue = [&](int kt) {
        int buf = kt & 3;
        #pragma unroll
        for (int i = 0; i < 2; i++) {
            int ch = tid + 256 * i;            // 512 chunks: 32 k-rows x 16
            int k = ch >> 4, q = ch & 15;
            CP16(sA + buf * T1H + (k * 136 + q * 8) * 2,
                 Ag + (size_t)(kt * 32 + k) * E_ + acol + q * 8);
            CP16(sB + buf * T1H + (k * 136 + q * 8) * 2,
                 Bg + (size_t)(kt * 32 + k) * C_ + q * 8);
        }
        CP_COMMIT();
    };

    const int KT = N_ / 32;   // 128
    issue(0); issue(1); issue(2);

    for (int kt = 0; kt < KT; kt++) {
        int rem = KT - 1 - kt;
        if (rem >= 2)      CP_WAIT(2);
        else if (rem == 1) CP_WAIT(1);
        else               CP_WAIT(0);
        __syncthreads();

        const __half* As = (const __half*)(ds + (size_t)(kt & 3) * T1H);
        const uint32_t sAb = sA + (uint32_t)(kt & 3) * T1H;
        const uint32_t sBb = sB + (uint32_t)(kt & 3) * T1H;

        {   // fused De from fp16 H tile (error ~1e-5 vs raw, within budget)
            float s = 0.f;
            #pragma unroll
            for (int k = 0; k < 16; k++)
                s += __half2float(As[(half * 16 + k) * 136 + mcol]);
            deacc += s;
        }

        #pragma unroll
        for (int kc = 0; kc < 32; kc += 16) {
            uint32_t af[4][4], bf[4][2];
            #pragma unroll
            for (int mt = 0; mt < 4; mt++) {
                // trans x4: quads (m0,k0)(m0+8,k0)(m0,k0+8)(m0+8,k0+8) -> a regs in order
                uint32_t addr = sAb + offT + (uint32_t)((kc * 136 + wm * 64 + mt * 16) * 2);
                LDSM4T(af[mt][0], af[mt][1], af[mt][2], af[mt][3], addr);
            }
            #pragma unroll
            for (int p = 0; p < 2; p++) {
                uint32_t d0, d1, d2, d3;
                uint32_t addr = sBb + offT + (uint32_t)((kc * 136 + wn * 32 + p * 16) * 2);
                LDSM4T(d0, d1, d2, d3, addr);
                bf[2 * p][0] = d0; bf[2 * p + 1][0] = d1;
                bf[2 * p][1] = d2; bf[2 * p + 1][1] = d3;
            }
            #pragma unroll
            for (int mt = 0; mt < 4; mt++)
                #pragma unroll
                for (int nt = 0; nt < 4; nt++)
                    mma_f16(acc[mt][nt], af[mt], bf[nt]);
        }

        if (kt + 3 < KT) issue(kt + 3);
    }

    // ---- epilogue: De combine, M->fp16 smem, W fp16 smem, sub-GEMM M2T=W M^T ----
    __half* Msm = (__half*)ds;                   // [128][136]h = 34816B (A-ring)
    const uint32_t sM = sA;
    const uint32_t sW = sA + 4 * T1H;            // [128][136]h (B-ring)

    deP[half][mcol] = deacc;
    __syncthreads();                             // all compute done
    {
        #pragma unroll
        for (int i = 0; i < 8; i++) {
            int ch = tid + 256 * i;              // 2048 chunks: 128 rows x 16
            int m = ch >> 4, q = ch & 15;
            CP16(sW + (uint32_t)((m * 136 + q * 8) * 2), g_Wh + (size_t)m * C_ + q * 8);
        }
        CP_COMMIT();
    }
    if (tid < 128) scl[tid] = 1.0f / (deP[0][tid] + deP[1][tid] + EPS);
    __syncthreads();

    #pragma unroll
    for (int mt = 0; mt < 4; mt++) {
        int rr = wm * 64 + mt * 16 + g;
        float s0 = scl[rr], s1 = scl[rr + 8];
        #pragma unroll
        for (int nt = 0; nt < 4; nt++) {
            int col = wn * 32 + nt * 8 + tg * 2;
            float* c = acc[mt][nt];
            *(uint32_t*)(Msm + rr * 136 + col)       = h2u(c[0] * s0, c[1] * s0);
            *(uint32_t*)(Msm + (rr + 8) * 136 + col) = h2u(c[2] * s1, c[3] * s1);
        }
    }
    CP_WAIT(0);
    __syncthreads();

    float acc2[4][4][4];
    #pragma unroll
    for (int i = 0; i < 4; i++)
        #pragma unroll
        for (int j = 0; j < 4; j++)
            #pragma unroll
            for (int rr = 0; rr < 4; rr++) acc2[i][j][rr] = 0.f;

    // non-trans LDSM per-lane offset for [m][k] stride-136h tiles
    const uint32_t offN = (uint32_t)(((q0 * 8 + r8) * 136 + q1 * 8) * 2);

    #pragma unroll
    for (int kc = 0; kc < 128; kc += 16) {
        uint32_t af[4][4], bf[4][2];
        #pragma unroll
        for (int mt = 0; mt < 4; mt++) {
            uint32_t addr = sW + offN + (uint32_t)(((wm * 64 + mt * 16) * 136 + kc) * 2);
            LDSM4(af[mt][0], af[mt][1], af[mt][2], af[mt][3], addr);
        }
        #pragma unroll
        for (int p = 0; p < 2; p++) {
            uint32_t d0, d1, d2, d3;
            uint32_t addr = sM + offN + (uint32_t)(((wn * 32 + p * 16) * 136 + kc) * 2);
            LDSM4(d0, d1, d2, d3, addr);
            bf[2 * p][0] = d0; bf[2 * p + 1][0] = d1;
            bf[2 * p][1] = d2; bf[2 * p + 1][1] = d3;
        }
        #pragma unroll
        for (int mt = 0; mt < 4; mt++)
            #pragma unroll
            for (int nt = 0; nt < 4; nt++)
                mma_f16(acc2[mt][nt], af[mt], bf[nt]);
    }

    #pragma unroll
    for (int mt = 0; mt < 4; mt++) {
        int c2 = wm * 64 + mt * 16 + g;
        #pragma unroll
        for (int nt = 0; nt < 4; nt++) {
            int e = wn * 32 + nt * 8 + tg * 2;
            float* c = acc2[mt][nt];
            *(uint32_t*)(g_M2Th + ((size_t)b * C_ + c2) * E_ + blk * 128 + e) =
                h2u(c[0], c[1]);
            *(uint32_t*)(g_M2Th + ((size_t)b * C_ + c2 + 8) * E_ + blk * 128 + e) =
                h2u(c[2], c[3]);
        }
    }
}

// ---------------- GEMM3: [m][k] fp16 both, STG=4, 2 CTAs/SM ------------------
#define T3H (128 * 40 * 2)         // 10240 bytes per tile
#define DYN3 (4 * 2 * T3H)         // 81920

__global__ __launch_bounds__(256, 2) void gemm3_kernel(const float* __restrict__ biasg,
                                                       float* __restrict__ Og) {
    extern __shared__ __align__(16) char ds[];
    __shared__ float scl[128];

    const int tid = threadIdx.x, b = blockIdx.z, blk = blockIdx.x;
    const int lane = tid & 31, wid = tid >> 5;
    const int g = lane >> 2, tg = lane & 3;
    const int wm = wid & 1, wn = wid >> 1;
    const int r8 = lane & 7, q0 = (lane >> 3) & 1, q1 = (lane >> 4) & 1;

    const __half* Ag = g_Hh + ((size_t)b * N_ + blk * 128) * E_;
    const __half* Bg = g_M2Th + (size_t)b * C_ * E_;

    if (tid < 128) scl[tid] = biasg[tid];

    const uint32_t sA = smem_u32(ds), sB = sA + 4 * T3H;
    const uint32_t offN = (uint32_t)(((q0 * 8 + r8) * 40 + q1 * 8) * 2);

    float acc[4][4][4];
    #pragma unroll
    for (int i = 0; i < 4; i++)
        #pragma unroll
        for (int j = 0; j < 4; j++)
            #pragma unroll
            for (int rr = 0; rr < 4; rr++) acc[i][j][rr] = 0.f;

    auto issue = [&](int kt) {
        int buf = kt & 3;
        #pragma unroll
        for (int i = 0; i < 2; i++) {
            int ch = tid + 256 * i;            // 512 chunks: 128 rows x 4
            int m = ch >> 2, q = ch & 3;
            CP16(sA + buf * T3H + (m * 40 + q * 8) * 2,
                 Ag + (size_t)m * E_ + kt * 32 + q * 8);
            CP16(sB + buf * T3H + (m * 40 + q * 8) * 2,
                 Bg + (size_t)m * E_ + kt * 32 + q * 8);
        }
        CP_COMMIT();
    };

    const int KT = E_ / 32;   // 64
    issue(0); issue(1); issue(2);

    for (int kt = 0; kt < KT; kt++) {
        int rem = KT - 1 - kt;
        if (rem >= 2)      CP_WAIT(2);
        else if (rem == 1) CP_WAIT(1);
        else               CP_WAIT(0);
        __syncthreads();

        const uint32_t sAb = sA + (uint32_t)(kt & 3) * T3H;
        const uint32_t sBb = sB + (uint32_t)(kt & 3) * T3H;

        #pragma unroll
        for (int kc = 0; kc < 32; kc += 16) {
            uint32_t af[4][4], bf[4][2];
            #pragma unroll
            for (int mt = 0; mt < 4; mt++) {
                uint32_t addr = sAb + offN + (uint32_t)(((wm * 64 + mt * 16) * 40 + kc) * 2);
                LDSM4(af[mt][0], af[mt][1], af[mt][2], af[mt][3], addr);
            }
            #pragma unroll
            for (int p = 0; p < 2; p++) {
                uint32_t d0, d1, d2, d3;
                uint32_t addr = sBb + offN + (uint32_t)(((wn * 32 + p * 16) * 40 + kc) * 2);
                LDSM4(d0, d1, d2, d3, addr);
                bf[2 * p][0] = d0; bf[2 * p + 1][0] = d1;
                bf[2 * p][1] = d2; bf[2 * p + 1][1] = d3;
            }
            #pragma unroll
            for (int mt = 0; mt < 4; mt++)
                #pragma unroll
                for (int nt = 0; nt < 4; nt++)
                    mma_f16(acc[mt][nt], af[mt], bf[nt]);
        }

        if (kt + 3 < KT) issue(kt + 3);
    }

    #pragma unroll
    for (int mt = 0; mt < 4; mt++) {
        int rr = wm * 64 + mt * 16 + g;
        float s0 = g_DvInv[b * N_ + blk * 128 + rr];
        float s1 = g_DvInv[b * N_ + blk * 128 + rr + 8];
        #pragma unroll
        for (int nt = 0; nt < 4; nt++) {
            int col = wn * 32 + nt * 8 + tg * 2;
            float b0 = scl[col], b1 = scl[col + 1];
            float* c = acc[mt][nt];
            *(float2*)(Og + ((size_t)b * N_ + blk * 128 + rr) * C_ + col) =
                make_float2(c[0] * s0 + b0, c[1] * s0 + b1);
            *(float2*)(Og + ((size_t)b * N_ + blk * 128 + rr + 8) * C_ + col) =
                make_float2(c[2] * s1 + b0, c[3] * s1 + b1);
        }
    }
}

// ---------------- launch -----------------------------------------------------
extern "C" void kernel_launch(void* const* d_in, const int* in_sizes, int n_in,
                              void* d_out, int out_size) {
    const float *x = nullptr, *H = nullptr, *W = nullptr, *bias = nullptr;
    for (int i = 0; i < n_in; i++) {
        long long s = in_sizes[i];
        if (s == (long long)B_ * N_ * E_)      H = (const float*)d_in[i];
        else if (s == (long long)B_ * N_ * C_) x = (const float*)d_in[i];
        else if (s == (long long)C_ * C_)      W = (const float*)d_in[i];
        else if (s == (long long)C_)           bias = (const float*)d_in[i];
    }
    float* outp = (float*)d_out;

    cudaFuncSetAttribute(gemm1_kernel, cudaFuncAttributeMaxDynamicSharedMemorySize, DYN1);
    cudaFuncSetAttribute(gemm3_kernel, cudaFuncAttributeMaxDynamicSharedMemorySize, DYN3);

    prep_h<<<B_ * N_ / 8, dim3(32, 8)>>>(H);               // Hh + Dv
    prep_x<<<(B_ * N_ * C_ / 4) / 256, 256>>>(x);          // Xh
    prep_w<<<(C_ * C_ / 4) / 256, 256>>>(W);               // Wh

    // M2Th = W (De^-1 H^T (Dv^-1/2 x))^T   [gemm1 + fused De + fused linear]
    gemm1_kernel<<<dim3(E_ / 128, 1, B_), 256, DYN1>>>();
    // out = Dv^-1/2 (H M2) + bias
    gemm3_kernel<<<dim3(N_ / 128, 1, B_), 256, DYN3>>>(bias, outp);
}

// round 15
// speedup vs baseline: 1.7360x; 1.0087x over previous
#include <cuda_runtime.h>
#include <cuda_fp16.h>
#include <cstdint>

// BatchedHGNNLayer: out = diag(Dv^-1/2) H diag(De^-1) H^T diag(Dv^-1/2) x W^T + b
// B=8, N=4096, E=2048, C=128 fp32 in/out.
// FP16 m16n8k16 pipeline. This round: gemm1 BM=64, 2 CTAs/SM (256 CTAs).

#define B_ 8
#define N_ 4096
#define E_ 2048
#define C_ 128
#define EPS 1e-6f

// ---------------- scratch ----------------------------------------------------
__device__ float  g_DvInv[B_ * N_];
__device__ __half g_Hh[(size_t)B_ * N_ * E_];     // fp16(H)            [b][n][e]
__device__ __half g_Xh[(size_t)B_ * N_ * C_];     // fp16(x * DvInv)    [b][n][c]
__device__ __half g_Wh[C_ * C_];                  // fp16(W)
__device__ __half g_M2Th[(size_t)B_ * C_ * E_];   // fp16((De^-1 H^T Xs) W^T)^T [b][c2][e]

// ---------------- helpers ----------------------------------------------------
__device__ __forceinline__ uint32_t smem_u32(const void* p) {
    uint32_t a;
    asm("{ .reg .u64 t; cvta.to.shared.u64 t, %1; cvt.u32.u64 %0, t; }" : "=r"(a) : "l"(p));
    return a;
}
__device__ __forceinline__ uint32_t h2u(float a, float b) {
    __half2 h = __floats2half2_rn(a, b);
    return *(uint32_t*)&h;
}
__device__ __forceinline__ void mma_f16(float* c, const uint32_t* a, const uint32_t* b) {
    asm volatile(
        "mma.sync.aligned.m16n8k16.row.col.f32.f16.f16.f32 "
        "{%0,%1,%2,%3}, {%4,%5,%6,%7}, {%8,%9}, {%0,%1,%2,%3};"
        : "+f"(c[0]), "+f"(c[1]), "+f"(c[2]), "+f"(c[3])
        : "r"(a[0]), "r"(a[1]), "r"(a[2]), "r"(a[3]), "r"(b[0]), "r"(b[1]));
}
#define CP16(dst, src) \
    asm volatile("cp.async.cg.shared.global [%0], [%1], 16;" :: "r"(dst), "l"(src))
#define CP_COMMIT() asm volatile("cp.async.commit_group;" ::: "memory")
#define CP_WAIT(n)  asm volatile("cp.async.wait_group %0;" :: "n"(n) : "memory")
#define LDSM4(r0, r1, r2, r3, addr)                                             \
    asm volatile("ldmatrix.sync.aligned.m8n8.x4.shared.b16 {%0,%1,%2,%3}, [%4];"\
                 : "=r"(r0), "=r"(r1), "=r"(r2), "=r"(r3) : "r"(addr))
#define LDSM4T(r0, r1, r2, r3, addr)                                            \
    asm volatile("ldmatrix.sync.aligned.m8n8.x4.trans.shared.b16 {%0,%1,%2,%3}, [%4];"\
                 : "=r"(r0), "=r"(r1), "=r"(r2), "=r"(r3) : "r"(addr))

// ---------------- prep kernels ------------------------------------------------
__global__ void prep_h(const float* __restrict__ Hg) {
    int row = blockIdx.x * 8 + threadIdx.y;
    const float4* src = (const float4*)(Hg + (size_t)row * E_);
    uint2* dst = (uint2*)(g_Hh + (size_t)row * E_);
    float s = 0.f;
    for (int i = threadIdx.x; i < E_ / 4; i += 32) {
        float4 v = src[i];
        s += (v.x + v.y) + (v.z + v.w);
        uint2 u; u.x = h2u(v.x, v.y); u.y = h2u(v.z, v.w);
        dst[i] = u;
    }
    #pragma unroll
    for (int o = 16; o; o >>= 1) s += __shfl_xor_sync(0xffffffffu, s, o);
    if (threadIdx.x == 0) g_DvInv[row] = rsqrtf(s + EPS);
}

__global__ void prep_x(const float* __restrict__ xg) {
    int i = blockIdx.x * 256 + threadIdx.x;     // f4 index
    int row = i >> 5;
    float dv = g_DvInv[row];
    float4 v = ((const float4*)xg)[i];
    uint2 u; u.x = h2u(v.x * dv, v.y * dv); u.y = h2u(v.z * dv, v.w * dv);
    ((uint2*)g_Xh)[i] = u;
}

__global__ void prep_w(const float* __restrict__ Wg) {
    int i = blockIdx.x * 256 + threadIdx.x;     // 4096 f4
    float4 v = ((const float4*)Wg)[i];
    uint2 u; u.x = h2u(v.x, v.y); u.y = h2u(v.z, v.w);
    ((uint2*)g_Wh)[i] = u;
}

// ---------------- GEMM1: BM=64, [k][m] fp16, 2 CTAs/SM -----------------------
// M2Th[c2][e-64tile] = sum_c W[c2][c] * (De^-1 sum_n H[n][e] Xs[n][c])[e][c]
#define TA1 (32 * 72 * 2)          // 4608
#define TB1 (32 * 136 * 2)         // 8704
#define DYN1 (4 * TA1 + 4 * TB1)   // 53248

__global__ __launch_bounds__(256, 2) void gemm1_kernel() {
    extern __shared__ __align__(16) char ds[];
    __shared__ float deP[4][64];
    __shared__ float scl[64];

    const int tid = threadIdx.x, b = blockIdx.z, blk = blockIdx.x;
    const int lane = tid & 31, wid = tid >> 5;
    const int g = lane >> 2, tg = lane & 3;
    const int wm = wid & 1, wn = wid >> 1;
    const int r8 = lane & 7, q0 = (lane >> 3) & 1, q1 = (lane >> 4) & 1;

    const __half* Ag = g_Hh + (size_t)b * N_ * E_;
    const __half* Bg = g_Xh + (size_t)b * N_ * C_;
    const int acol = blk * 64;

    const uint32_t sA = smem_u32(ds), sB = sA + 4 * TA1;
    // trans-LDSM per-lane offset: A tiles stride 72h, B tiles stride 136h
    const uint32_t offTA = (uint32_t)(((q1 * 8 + r8) * 72 + q0 * 8) * 2);
    const uint32_t offTB = (uint32_t)(((q1 * 8 + r8) * 136 + q0 * 8) * 2);

    float acc[2][4][4];
    #pragma unroll
    for (int i = 0; i < 2; i++)
        #pragma unroll
        for (int j = 0; j < 4; j++)
            #pragma unroll
            for (int rr = 0; rr < 4; rr++) acc[i][j][rr] = 0.f;

    float deacc = 0.f;
    const int mcol = tid & 63, kgrp = tid >> 6;   // 4 groups of 8 k-rows

    auto issue = [&](int kt) {
        int buf = kt & 3;
        {   // A: 32 k-rows x 64m fp16 = 256 chunks of 16B, 1/thread
            int k = tid >> 3, q = tid & 7;
            CP16(sA + buf * TA1 + (k * 72 + q * 8) * 2,
                 Ag + (size_t)(kt * 32 + k) * E_ + acol + q * 8);
        }
        #pragma unroll
        for (int i = 0; i < 2; i++) {   // B: 32 k-rows x 128c = 512 chunks
            int ch = tid + 256 * i;
            int k = ch >> 4, q = ch & 15;
            CP16(sB + buf * TB1 + (k * 136 + q * 8) * 2,
                 Bg + (size_t)(kt * 32 + k) * C_ + q * 8);
        }
        CP_COMMIT();
    };

    const int KT = N_ / 32;   // 128
    issue(0); issue(1); issue(2);

    for (int kt = 0; kt < KT; kt++) {
        int rem = KT - 1 - kt;
        if (rem >= 2)      CP_WAIT(2);
        else if (rem == 1) CP_WAIT(1);
        else               CP_WAIT(0);
        __syncthreads();

        const __half* As = (const __half*)(ds + (size_t)(kt & 3) * TA1);
        const uint32_t sAb = sA + (uint32_t)(kt & 3) * TA1;
        const uint32_t sBb = sB + (uint32_t)(kt & 3) * TB1;

        {   // fused De: column sums of the 32x64 H tile
            float s = 0.f;
            #pragma unroll
            for (int k = 0; k < 8; k++)
                s += __half2float(As[(kgrp * 8 + k) * 72 + mcol]);
            deacc += s;
        }

        #pragma unroll
        for (int kc = 0; kc < 32; kc += 16) {
            uint32_t af[2][4], bf[4][2];
            #pragma unroll
            for (int mt = 0; mt < 2; mt++) {
                uint32_t addr = sAb + offTA + (uint32_t)((kc * 72 + wm * 32 + mt * 16) * 2);
                LDSM4T(af[mt][0], af[mt][1], af[mt][2], af[mt][3], addr);
            }
            #pragma unroll
            for (int p = 0; p < 2; p++) {
                uint32_t d0, d1, d2, d3;
                uint32_t addr = sBb + offTB + (uint32_t)((kc * 136 + wn * 32 + p * 16) * 2);
                LDSM4T(d0, d1, d2, d3, addr);
                bf[2 * p][0] = d0; bf[2 * p + 1][0] = d1;
                bf[2 * p][1] = d2; bf[2 * p + 1][1] = d3;
            }
            #pragma unroll
            for (int mt = 0; mt < 2; mt++)
                #pragma unroll
                for (int nt = 0; nt < 4; nt++)
                    mma_f16(acc[mt][nt], af[mt], bf[nt]);
        }

        if (kt + 3 < KT) issue(kt + 3);
    }

    // ---- epilogue: De, M->smem fp16, W->smem, sub-GEMM M2T = W M^T ----
    __half* Msm = (__half*)ds;                   // [64][136]h = 17408B (A-ring 18432B)
    const uint32_t sM = sA;
    const uint32_t sW = sA + 4 * TA1;            // [128][136]h = 34816B (B-ring 34816B)

    deP[kgrp][mcol] = deacc;
    __syncthreads();                             // all compute done; rings reusable
    {
        #pragma unroll
        for (int i = 0; i < 8; i++) {
            int ch = tid + 256 * i;              // 2048 chunks: 128 rows x 16
            int m = ch >> 4, q = ch & 15;
            CP16(sW + (uint32_t)((m * 136 + q * 8) * 2), g_Wh + (size_t)m * C_ + q * 8);
        }
        CP_COMMIT();
    }
    if (tid < 64)
        scl[tid] = 1.0f / (deP[0][tid] + deP[1][tid] + deP[2][tid] + deP[3][tid] + EPS);
    __syncthreads();

    // Msm[e][c] layout, stride 136h
    #pragma unroll
    for (int mt = 0; mt < 2; mt++) {
        int rr = wm * 32 + mt * 16 + g;
        float s0 = scl[rr], s1 = scl[rr + 8];
        #pragma unroll
        for (int nt = 0; nt < 4; nt++) {
            int col = wn * 32 + nt * 8 + tg * 2;
            float* c = acc[mt][nt];
            *(uint32_t*)(Msm + rr * 136 + col)       = h2u(c[0] * s0, c[1] * s0);
            *(uint32_t*)(Msm + (rr + 8) * 136 + col) = h2u(c[2] * s1, c[3] * s1);
        }
    }
    CP_WAIT(0);
    __syncthreads();

    float acc2[4][2][4];
    #pragma unroll
    for (int i = 0; i < 4; i++)
        #pragma unroll
        for (int j = 0; j < 2; j++)
            #pragma unroll
            for (int rr = 0; rr < 4; rr++) acc2[i][j][rr] = 0.f;

    const uint32_t offN = (uint32_t)(((q0 * 8 + r8) * 136 + q1 * 8) * 2);

    #pragma unroll
    for (int kc = 0; kc < 128; kc += 16) {
        uint32_t af[4][4], bf[2][2];
        #pragma unroll
        for (int mt = 0; mt < 4; mt++) {
            uint32_t addr = sW + offN + (uint32_t)(((wm * 64 + mt * 16) * 136 + kc) * 2);
            LDSM4(af[mt][0], af[mt][1], af[mt][2], af[mt][3], addr);
        }
        {
            uint32_t d0, d1, d2, d3;
            uint32_t addr = sM + offN + (uint32_t)((wn * 16 * 136 + kc) * 2);
            LDSM4(d0, d1, d2, d3, addr);
            bf[0][0] = d0; bf[1][0] = d1;
            bf[0][1] = d2; bf[1][1] = d3;
        }
        #pragma unroll
        for (int mt = 0; mt < 4; mt++)
            #pragma unroll
            for (int nt = 0; nt < 2; nt++)
                mma_f16(acc2[mt][nt], af[mt], bf[nt]);
    }

    #pragma unroll
    for (int mt = 0; mt < 4; mt++) {
        int c2 = wm * 64 + mt * 16 + g;
        #pragma unroll
        for (int nt = 0; nt < 2; nt++) {
            int e = wn * 16 + nt * 8 + tg * 2;
            float* c = acc2[mt][nt];
            *(uint32_t*)(g_M2Th + ((size_t)b * C_ + c2) * E_ + blk * 64 + e) =
                h2u(c[0], c[1]);
            *(uint32_t*)(g_M2Th + ((size_t)b * C_ + c2 + 8) * E_ + blk * 64 + e) =
                h2u(c[2], c[3]);
        }
    }
}

// ---------------- GEMM3: [m][k] fp16 both, STG=4, 2 CTAs/SM (unchanged) ------
#define T3H (128 * 40 * 2)         // 10240 bytes per tile
#define DYN3 (4 * 2 * T3H)         // 81920

__global__ __launch_bounds__(256, 2) void gemm3_kernel(const float* __restrict__ biasg,
                                                       float* __restrict__ Og) {
    extern __shared__ __align__(16) char ds[];
    __shared__ float scl[128];

    const int tid = threadIdx.x, b = blockIdx.z, blk = blockIdx.x;
    const int lane = tid & 31, wid = tid >> 5;
    const int g = lane >> 2, tg = lane & 3;
    const int wm = wid & 1, wn = wid >> 1;
    const int r8 = lane & 7, q0 = (lane >> 3) & 1, q1 = (lane >> 4) & 1;

    const __half* Ag = g_Hh + ((size_t)b * N_ + blk * 128) * E_;
    const __half* Bg = g_M2Th + (size_t)b * C_ * E_;

    if (tid < 128) scl[tid] = biasg[tid];

    const uint32_t sA = smem_u32(ds), sB = sA + 4 * T3H;
    const uint32_t offN = (uint32_t)(((q0 * 8 + r8) * 40 + q1 * 8) * 2);

    float acc[4][4][4];
    #pragma unroll
    for (int i = 0; i < 4; i++)
        #pragma unroll
        for (int j = 0; j < 4; j++)
            #pragma unroll
            for (int rr = 0; rr < 4; rr++) acc[i][j][rr] = 0.f;

    auto issue = [&](int kt) {
        int buf = kt & 3;
        #pragma unroll
        for (int i = 0; i < 2; i++) {
            int ch = tid + 256 * i;            // 512 chunks: 128 rows x 4
            int m = ch >> 2, q = ch & 3;
            CP16(sA + buf * T3H + (m * 40 + q * 8) * 2,
                 Ag + (size_t)m * E_ + kt * 32 + q * 8);
            CP16(sB + buf * T3H + (m * 40 + q * 8) * 2,
                 Bg + (size_t)m * E_ + kt * 32 + q * 8);
        }
        CP_COMMIT();
    };

    const int KT = E_ / 32;   // 64
    issue(0); issue(1); issue(2);

    for (int kt = 0; kt < KT; kt++) {
        int rem = KT - 1 - kt;
        if (rem >= 2)      CP_WAIT(2);
        else if (rem == 1) CP_WAIT(1);
        else               CP_WAIT(0);
        __syncthreads();

        const uint32_t sAb = sA + (uint32_t)(kt & 3) * T3H;
        const uint32_t sBb = sB + (uint32_t)(kt & 3) * T3H;

        #pragma unroll
        for (int kc = 0; kc < 32; kc += 16) {
            uint32_t af[4][4], bf[4][2];
            #pragma unroll
            for (int mt = 0; mt < 4; mt++) {
                uint32_t addr = sAb + offN + (uint32_t)(((wm * 64 + mt * 16) * 40 + kc) * 2);
                LDSM4(af[mt][0], af[mt][1], af[mt][2], af[mt][3], addr);
            }
            #pragma unroll
            for (int p = 0; p < 2; p++) {
                uint32_t d0, d1, d2, d3;
                uint32_t addr = sBb + offN + (uint32_t)(((wn * 32 + p * 16) * 40 + kc) * 2);
                LDSM4(d0, d1, d2, d3, addr);
                bf[2 * p][0] = d0; bf[2 * p + 1][0] = d1;
                bf[2 * p][1] = d2; bf[2 * p + 1][1] = d3;
            }
            #pragma unroll
            for (int mt = 0; mt < 4; mt++)
                #pragma unroll
                for (int nt = 0; nt < 4; nt++)
                    mma_f16(acc[mt][nt], af[mt], bf[nt]);
        }

        if (kt + 3 < KT) issue(kt + 3);
    }

    #pragma unroll
    for (int mt = 0; mt < 4; mt++) {
        int rr = wm * 64 + mt * 16 + g;
        float s0 = g_DvInv[b * N_ + blk * 128 + rr];
        float s1 = g_DvInv[b * N_ + blk * 128 + rr + 8];
        #pragma unroll
        for (int nt = 0; nt < 4; nt++) {
            int col = wn * 32 + nt * 8 + tg * 2;
            float b0 = scl[col], b1 = scl[col + 1];
            float* c = acc[mt][nt];
            *(float2*)(Og + ((size_t)b * N_ + blk * 128 + rr) * C_ + col) =
                make_float2(c[0] * s0 + b0, c[1] * s0 + b1);
            *(float2*)(Og + ((size_t)b * N_ + blk * 128 + rr + 8) * C_ + col) =
                make_float2(c[2] * s1 + b0, c[3] * s1 + b1);
        }
    }
}

// ---------------- launch -----------------------------------------------------
extern "C" void kernel_launch(void* const* d_in, const int* in_sizes, int n_in,
                              void* d_out, int out_size) {
    const float *x = nullptr, *H = nullptr, *W = nullptr, *bias = nullptr;
    for (int i = 0; i < n_in; i++) {
        long long s = in_sizes[i];
        if (s == (long long)B_ * N_ * E_)      H = (const float*)d_in[i];
        else if (s == (long long)B_ * N_ * C_) x = (const float*)d_in[i];
        else if (s == (long long)C_ * C_)      W = (const float*)d_in[i];
        else if (s == (long long)C_)           bias = (const float*)d_in[i];
    }
    float* outp = (float*)d_out;

    cudaFuncSetAttribute(gemm1_kernel, cudaFuncAttributeMaxDynamicSharedMemorySize, DYN1);
    cudaFuncSetAttribute(gemm3_kernel, cudaFuncAttributeMaxDynamicSharedMemorySize, DYN3);

    prep_h<<<B_ * N_ / 8, dim3(32, 8)>>>(H);               // Hh + Dv
    prep_x<<<(B_ * N_ * C_ / 4) / 256, 256>>>(x);          // Xh
    prep_w<<<(C_ * C_ / 4) / 256, 256>>>(W);               // Wh

    // M2Th = W (De^-1 H^T (Dv^-1/2 x))^T   [gemm1 + fused De + fused linear]
    gemm1_kernel<<<dim3(E_ / 64, 1, B_), 256, DYN1>>>();
    // out = Dv^-1/2 (H M2) + bias
    gemm3_kernel<<<dim3(N_ / 128, 1, B_), 256, DYN3>>>(bias, outp);
}